// round 3
// baseline (speedup 1.0000x reference)
#include <cuda_runtime.h>
#include <cuda_bf16.h>

// ROI classifier head == 3-layer MLP (the sort/unsort is an identity permutation
// because batch_indices is pre-sorted).
//   buf1 = relu(X @ W1 + b1)   X:[2048,12544] W1:[12544,1024]
//   buf2 = relu(buf1 @ W2 + b2)            W2:[1024,1024]
//   out  = buf2 @ Wc + bc                  Wc:[1024,81]

#define MROWS 2048
#define KFEAT 12544
#define HID   1024
#define NCLS  81

#define BM 128
#define BN 64
#define BK 16
#define TM 8
#define TN 4
#define NTHREADS 256   // (BM/TM)*(BN/TN)

__device__ float g_buf1[MROWS * HID];
__device__ float g_buf2[MROWS * HID];

__global__ __launch_bounds__(NTHREADS) void sgemm_bias_act(
    const float* __restrict__ A, const float* __restrict__ B,
    const float* __restrict__ bias, float* __restrict__ C,
    int M, int N, int K, int doRelu)
{
    __shared__ float As[BK][BM];
    __shared__ float Bs[BK][BN];

    const int tid = threadIdx.x;
    const int bm0 = blockIdx.y * BM;
    const int bn0 = blockIdx.x * BN;

    const int ty = tid / (BN / TN);   // 0..15 -> row group of 8
    const int tx = tid % (BN / TN);   // 0..15 -> col group of 4

    float acc[TM][TN];
    #pragma unroll
    for (int i = 0; i < TM; i++)
        #pragma unroll
        for (int j = 0; j < TN; j++) acc[i][j] = 0.f;

    // A-load mapping: 2 float4 per thread (128x16 tile = 512 float4)
    const int aRow0 = tid >> 2;       // 0..63
    const int aKq   = tid & 3;        // which float4 along K
    // B-load mapping: 1 float4 per thread (16x64 tile = 256 float4)
    const int bKrow = tid >> 4;       // 0..15
    const int bCol4 = tid & 15;       // 0..15

    const int nk = K / BK;
    for (int t = 0; t < nk; t++) {
        const int kt = t * BK;
        #pragma unroll
        for (int r = 0; r < 2; r++) {
            const int row = aRow0 + r * 64;
            float4 v = *reinterpret_cast<const float4*>(
                &A[(size_t)(bm0 + row) * K + kt + aKq * 4]);
            As[aKq * 4 + 0][row] = v.x;
            As[aKq * 4 + 1][row] = v.y;
            As[aKq * 4 + 2][row] = v.z;
            As[aKq * 4 + 3][row] = v.w;
        }
        {
            float4 v = *reinterpret_cast<const float4*>(
                &B[(size_t)(kt + bKrow) * N + bn0 + bCol4 * 4]);
            *reinterpret_cast<float4*>(&Bs[bKrow][bCol4 * 4]) = v;
        }
        __syncthreads();

        #pragma unroll
        for (int k = 0; k < BK; k++) {
            float ra[TM], rb[TN];
            #pragma unroll
            for (int i = 0; i < TM; i++) ra[i] = As[k][ty * TM + i];
            #pragma unroll
            for (int j = 0; j < TN; j++) rb[j] = Bs[k][tx * TN + j];
            #pragma unroll
            for (int i = 0; i < TM; i++)
                #pragma unroll
                for (int j = 0; j < TN; j++)
                    acc[i][j] = fmaf(ra[i], rb[j], acc[i][j]);
        }
        __syncthreads();
    }

    #pragma unroll
    for (int i = 0; i < TM; i++) {
        const int row = bm0 + ty * TM + i;
        #pragma unroll
        for (int j = 0; j < TN; j++) {
            const int col = bn0 + tx * TN + j;
            float v = acc[i][j] + bias[col];
            if (doRelu) v = fmaxf(v, 0.f);
            C[(size_t)row * N + col] = v;
        }
    }
}

// Final small GEMM: out[row, c] = sum_k buf2[row,k]*Wc[k,c] + bc[c], N=81.
// One block per row; Wc (332 KB) stays L2-resident across all 2048 blocks.
__global__ __launch_bounds__(128) void gemm_cls(
    const float* __restrict__ A, const float* __restrict__ Wc,
    const float* __restrict__ bc, float* __restrict__ out)
{
    __shared__ float xs[HID];
    const int row = blockIdx.x;
    const float* a = A + (size_t)row * HID;
    for (int i = threadIdx.x; i < HID; i += 128)
        xs[i] = a[i];
    __syncthreads();

    const int c = threadIdx.x;
    if (c < NCLS) {
        float acc = bc[c];
        #pragma unroll 8
        for (int k = 0; k < HID; k++)
            acc = fmaf(xs[k], Wc[(size_t)k * NCLS + c], acc);
        out[(size_t)row * NCLS + c] = acc;
    }
}

extern "C" void kernel_launch(void* const* d_in, const int* in_sizes, int n_in,
                              void* d_out, int out_size)
{
    const float* X  = (const float*)d_in[0];
    // d_in[1] = batch_indices (already sorted -> identity permutation; unused)
    const float* W1 = (const float*)d_in[2];
    const float* b1 = (const float*)d_in[3];
    const float* W2 = (const float*)d_in[4];
    const float* b2 = (const float*)d_in[5];
    const float* Wc = (const float*)d_in[6];
    const float* bc = (const float*)d_in[7];
    float* out = (float*)d_out;

    float *buf1, *buf2;
    cudaGetSymbolAddress((void**)&buf1, g_buf1);
    cudaGetSymbolAddress((void**)&buf2, g_buf2);

    dim3 block(NTHREADS);
    dim3 grid(HID / BN, MROWS / BM);   // 16 x 16 = 256 blocks

    sgemm_bias_act<<<grid, block>>>(X,    W1, b1, buf1, MROWS, HID, KFEAT, 1);
    sgemm_bias_act<<<grid, block>>>(buf1, W2, b2, buf2, MROWS, HID, HID,   1);
    gemm_cls<<<MROWS, 128>>>(buf2, Wc, bc, out);
}

// round 5
// speedup vs baseline: 2.2870x; 2.2870x over previous
#include <cuda_runtime.h>
#include <cuda_bf16.h>
#include <cstdint>
#include <cstddef>

// ============================================================
// ROI classifier head = 3-layer MLP (sort/unsort is identity:
// batch_indices is pre-sorted).
//   L1: relu(X[2048,12544] @ W1[12544,1024] + b1)
//   L2: relu(h1 @ W2[1024,1024] + b2)
//   L3: h2 @ Wc[1024,81] + bc
// L1/L2 via mma.sync m16n8k16 bf16 (legacy HMMA path — tcgen05
// is unavailable: harness PTX target is compute_103, no 'a').
// Precision restored with bf16x2 split: a*b ~= ah*bh + ah*bl + al*bh.
// ============================================================

#define MROWS 2048
#define KFEAT 12544
#define HID   1024
#define NCLS  81

#define BM 128
#define BN 128
#define BK 32
#define NTHREADS 256
#define PADK 40                       // smem row pitch in bf16 elems (80 B)
#define TILE_SM_BYTES (128 * PADK * 2)      // 10240
#define STAGE_BYTES   (4 * TILE_SM_BYTES)   // Ah, Al, Bh, Bl
#define SMEM_TOTAL    (2 * STAGE_BYTES)     // 81920 (double buffer)

// -------- scratch (device globals; no allocation allowed) --------
__device__ __align__(128) __nv_bfloat16 g_Xh[MROWS * KFEAT];
__device__ __align__(128) __nv_bfloat16 g_Xl[MROWS * KFEAT];
__device__ __align__(128) __nv_bfloat16 g_W1h[HID * KFEAT];   // [N,K] = W1^T
__device__ __align__(128) __nv_bfloat16 g_W1l[HID * KFEAT];
__device__ __align__(128) __nv_bfloat16 g_W2h[HID * HID];     // [N,K] = W2^T
__device__ __align__(128) __nv_bfloat16 g_W2l[HID * HID];
__device__ __align__(128) __nv_bfloat16 g_B1h[MROWS * HID];
__device__ __align__(128) __nv_bfloat16 g_B1l[MROWS * HID];
__device__ __align__(128) __nv_bfloat16 g_B2h[MROWS * HID];
__device__ __align__(128) __nv_bfloat16 g_B2l[MROWS * HID];

// -------- helpers --------
__device__ __forceinline__ void cp_async16(void* dst_smem, const void* src) {
    uint32_t a;
    asm("{ .reg .u64 t; cvta.to.shared.u64 t, %1; cvt.u32.u64 %0, t; }"
        : "=r"(a) : "l"(dst_smem));
    asm volatile("cp.async.cg.shared.global [%0], [%1], 16;" :: "r"(a), "l"(src) : "memory");
}
__device__ __forceinline__ void cp_commit() {
    asm volatile("cp.async.commit_group;" ::: "memory");
}
template <int N> __device__ __forceinline__ void cp_wait() {
    asm volatile("cp.async.wait_group %0;" :: "n"(N) : "memory");
}
__device__ __forceinline__ void mma16816(float* c, const uint32_t* a, const uint32_t* b) {
    asm volatile(
        "mma.sync.aligned.m16n8k16.row.col.f32.bf16.bf16.f32 "
        "{%0,%1,%2,%3}, {%4,%5,%6,%7}, {%8,%9}, {%0,%1,%2,%3};"
        : "+f"(c[0]), "+f"(c[1]), "+f"(c[2]), "+f"(c[3])
        : "r"(a[0]), "r"(a[1]), "r"(a[2]), "r"(a[3]), "r"(b[0]), "r"(b[1]));
}
__device__ __forceinline__ void split2(float v, __nv_bfloat16& h, __nv_bfloat16& l) {
    h = __float2bfloat16(v);
    l = __float2bfloat16(v - __bfloat162float(h));
}

// ============================================================
// out = relu(A @ B^T + bias) with bf16x2 split, fp32 accum.
// A hi/lo: [M, Ktot] row-major.  B hi/lo: [N, Ktot] row-major.
// Output written as bf16 hi/lo, row stride HID.
// ============================================================
__global__ void __launch_bounds__(NTHREADS) mlp_gemm(
    const __nv_bfloat16* __restrict__ Ah, const __nv_bfloat16* __restrict__ Al,
    const __nv_bfloat16* __restrict__ Bh, const __nv_bfloat16* __restrict__ Bl,
    const float* __restrict__ bias,
    __nv_bfloat16* __restrict__ outH, __nv_bfloat16* __restrict__ outL,
    int Ktot)
{
    extern __shared__ char sm[];
    const int tid = threadIdx.x;
    const int bn0 = blockIdx.x * BN;
    const int bm0 = blockIdx.y * BM;

    const int w  = tid >> 5;
    const int m0 = (w >> 1) * 32;     // warp tile 32x64, warps 4(m) x 2(n)
    const int n0 = (w & 1) * 64;
    const int lane = tid & 31;
    const int g = lane >> 2;          // group id 0..7
    const int t = lane & 3;           // thread-in-group 0..3

    float acc[2][8][4];
    #pragma unroll
    for (int i = 0; i < 2; i++)
        #pragma unroll
        for (int j = 0; j < 8; j++)
            #pragma unroll
            for (int q = 0; q < 4; q++) acc[i][j][q] = 0.f;

    const __nv_bfloat16* srcs[4] = { Ah, Al, Bh, Bl };

    auto load_stage = [&](int kt, int s) {
        char* base = sm + s * STAGE_BYTES;
        #pragma unroll
        for (int i = 0; i < 8; i++) {
            const int tile = i >> 1;                       // 0:Ah 1:Al 2:Bh 3:Bl
            const int c = ((i & 1) << 8) + tid;            // 0..511
            const int row = c >> 2;                        // 0..127
            const int kc = c & 3;                          // 16B chunk along K
            const int grow = (tile < 2 ? bm0 : bn0) + row;
            cp_async16(base + tile * TILE_SM_BYTES + row * (PADK * 2) + kc * 16,
                       srcs[tile] + (size_t)grow * Ktot + kt + kc * 8);
        }
        cp_commit();
    };

    const int nT = Ktot / BK;
    load_stage(0, 0);

    for (int it = 0; it < nT; it++) {
        const int cur = it & 1;
        if (it + 1 < nT) {
            load_stage((it + 1) * BK, cur ^ 1);
            cp_wait<1>();
        } else {
            cp_wait<0>();
        }
        __syncthreads();

        const char* sAh = sm + cur * STAGE_BYTES;
        const char* sAl = sAh + TILE_SM_BYTES;
        const char* sBh = sAh + 2 * TILE_SM_BYTES;
        const char* sBl = sAh + 3 * TILE_SM_BYTES;

        #pragma unroll
        for (int ks = 0; ks < 2; ks++) {                   // two k16 steps in BK=32
            const int kb = ks * 16;
            uint32_t aH[2][4], aL[2][4], bH[8][2], bL[8][2];
            #pragma unroll
            for (int i = 0; i < 2; i++) {
                const int r  = m0 + i * 16 + g;
                const int o0 = r * (PADK * 2) + (kb + 2 * t) * 2;
                const int o8 = o0 + 8 * (PADK * 2);
                aH[i][0] = *(const uint32_t*)(sAh + o0);
                aH[i][1] = *(const uint32_t*)(sAh + o8);
                aH[i][2] = *(const uint32_t*)(sAh + o0 + 16);
                aH[i][3] = *(const uint32_t*)(sAh + o8 + 16);
                aL[i][0] = *(const uint32_t*)(sAl + o0);
                aL[i][1] = *(const uint32_t*)(sAl + o8);
                aL[i][2] = *(const uint32_t*)(sAl + o0 + 16);
                aL[i][3] = *(const uint32_t*)(sAl + o8 + 16);
            }
            #pragma unroll
            for (int j = 0; j < 8; j++) {
                const int r  = n0 + j * 8 + g;
                const int o0 = r * (PADK * 2) + (kb + 2 * t) * 2;
                bH[j][0] = *(const uint32_t*)(sBh + o0);
                bH[j][1] = *(const uint32_t*)(sBh + o0 + 16);
                bL[j][0] = *(const uint32_t*)(sBl + o0);
                bL[j][1] = *(const uint32_t*)(sBl + o0 + 16);
            }
            #pragma unroll
            for (int i = 0; i < 2; i++)
                #pragma unroll
                for (int j = 0; j < 8; j++) {
                    mma16816(acc[i][j], aH[i], bH[j]);
                    mma16816(acc[i][j], aH[i], bL[j]);
                    mma16816(acc[i][j], aL[i], bH[j]);
                }
        }
        __syncthreads();
    }

    // epilogue: bias + relu + bf16 hi/lo split, direct global store
    #pragma unroll
    for (int i = 0; i < 2; i++) {
        const int r0 = bm0 + m0 + i * 16 + g;
        #pragma unroll
        for (int j = 0; j < 8; j++) {
            const int col = bn0 + n0 + j * 8 + 2 * t;
            const float bia0 = bias[col], bia1 = bias[col + 1];
            #pragma unroll
            for (int half = 0; half < 2; half++) {
                const int r = r0 + half * 8;
                float v0 = fmaxf(acc[i][j][2 * half]     + bia0, 0.f);
                float v1 = fmaxf(acc[i][j][2 * half + 1] + bia1, 0.f);
                __nv_bfloat16 h0, l0, h1, l1;
                split2(v0, h0, l0); split2(v1, h1, l1);
                __nv_bfloat162 hh; hh.x = h0; hh.y = h1;
                __nv_bfloat162 ll; ll.x = l0; ll.y = l1;
                *reinterpret_cast<__nv_bfloat162*>(outH + (size_t)r * HID + col) = hh;
                *reinterpret_cast<__nv_bfloat162*>(outL + (size_t)r * HID + col) = ll;
            }
        }
    }
}

// ---------------- conversion kernels ----------------
__global__ void split_kernel(const float4* __restrict__ src,
                             __nv_bfloat162* __restrict__ h,
                             __nv_bfloat162* __restrict__ l, long n4)
{
    long i = blockIdx.x * (long)blockDim.x + threadIdx.x;
    const long stride = (long)gridDim.x * blockDim.x;
    for (; i < n4; i += stride) {
        float4 v = src[i];
        __nv_bfloat16 ha, la, hb, lb, hc, lc, hd, ld;
        split2(v.x, ha, la); split2(v.y, hb, lb);
        split2(v.z, hc, lc); split2(v.w, hd, ld);
        __nv_bfloat162 p0, p1, q0, q1;
        p0.x = ha; p0.y = hb; p1.x = hc; p1.y = hd;
        q0.x = la; q0.y = lb; q1.x = lc; q1.y = ld;
        h[2 * i] = p0; h[2 * i + 1] = p1;
        l[2 * i] = q0; l[2 * i + 1] = q1;
    }
}

// W[K,N] fp32 -> Th/Tl[N,K] bf16 (transpose + split)
__global__ void __launch_bounds__(256) transpose_split(
    const float* __restrict__ W, __nv_bfloat16* __restrict__ Th,
    __nv_bfloat16* __restrict__ Tl, int K, int N)
{
    __shared__ float tile[32][33];
    const int n0 = blockIdx.x * 32, k0 = blockIdx.y * 32;
    const int tx = threadIdx.x, ty = threadIdx.y;   // 32 x 8
    #pragma unroll
    for (int r = ty; r < 32; r += 8)
        tile[r][tx] = W[(size_t)(k0 + r) * N + n0 + tx];
    __syncthreads();
    #pragma unroll
    for (int r = ty; r < 32; r += 8) {
        float v = tile[tx][r];                       // = W[k0+tx][n0+r]
        __nv_bfloat16 h, l;
        split2(v, h, l);
        const size_t o = (size_t)(n0 + r) * K + k0 + tx;
        Th[o] = h; Tl[o] = l;
    }
}

// ---------------- final small GEMM (N=81) ----------------
__global__ void __launch_bounds__(128) gemm_cls(
    const __nv_bfloat16* __restrict__ Ah, const __nv_bfloat16* __restrict__ Al,
    const float* __restrict__ Wc, const float* __restrict__ bc,
    float* __restrict__ out)
{
    __shared__ float xs[HID];
    const int row = blockIdx.x;
    const size_t ro = (size_t)row * HID;
    for (int i = threadIdx.x; i < HID; i += 128)
        xs[i] = __bfloat162float(Ah[ro + i]) + __bfloat162float(Al[ro + i]);
    __syncthreads();
    const int c = threadIdx.x;
    if (c < NCLS) {
        float a = bc[c];
        #pragma unroll 8
        for (int k = 0; k < HID; k++)
            a = fmaf(xs[k], Wc[(size_t)k * NCLS + c], a);
        out[(size_t)row * NCLS + c] = a;
    }
}

// ---------------- launcher ----------------
extern "C" void kernel_launch(void* const* d_in, const int* in_sizes, int n_in,
                              void* d_out, int out_size)
{
    const float* X  = (const float*)d_in[0];
    // d_in[1] = batch_indices (sorted -> identity permutation; unused)
    const float* W1 = (const float*)d_in[2];
    const float* b1 = (const float*)d_in[3];
    const float* W2 = (const float*)d_in[4];
    const float* b2 = (const float*)d_in[5];
    const float* Wc = (const float*)d_in[6];
    const float* bc = (const float*)d_in[7];
    float* out = (float*)d_out;

    __nv_bfloat16 *Xh, *Xl, *W1h, *W1l, *W2h, *W2l, *B1h, *B1l, *B2h, *B2l;
    cudaGetSymbolAddress((void**)&Xh,  g_Xh);  cudaGetSymbolAddress((void**)&Xl,  g_Xl);
    cudaGetSymbolAddress((void**)&W1h, g_W1h); cudaGetSymbolAddress((void**)&W1l, g_W1l);
    cudaGetSymbolAddress((void**)&W2h, g_W2h); cudaGetSymbolAddress((void**)&W2l, g_W2l);
    cudaGetSymbolAddress((void**)&B1h, g_B1h); cudaGetSymbolAddress((void**)&B1l, g_B1l);
    cudaGetSymbolAddress((void**)&B2h, g_B2h); cudaGetSymbolAddress((void**)&B2l, g_B2l);

    cudaFuncSetAttribute(mlp_gemm, cudaFuncAttributeMaxDynamicSharedMemorySize, SMEM_TOTAL);

    // 1) input / weight conversion to bf16 hi/lo
    split_kernel<<<2048, 256>>>((const float4*)X, (__nv_bfloat162*)Xh,
                                (__nv_bfloat162*)Xl, (long)MROWS * KFEAT / 4);
    transpose_split<<<dim3(HID / 32, KFEAT / 32), dim3(32, 8)>>>(W1, W1h, W1l, KFEAT, HID);
    transpose_split<<<dim3(HID / 32, HID / 32),  dim3(32, 8)>>>(W2, W2h, W2l, HID, HID);

    // 2) GEMM1: [2048,12544] x [12544,1024]^T
    mlp_gemm<<<dim3(HID / BN, MROWS / BM), NTHREADS, SMEM_TOTAL>>>(
        Xh, Xl, W1h, W1l, b1, B1h, B1l, KFEAT);

    // 3) GEMM2: [2048,1024] x [1024,1024]^T
    mlp_gemm<<<dim3(HID / BN, MROWS / BM), NTHREADS, SMEM_TOTAL>>>(
        B1h, B1l, W2h, W2l, b2, B2h, B2l, HID);

    // 4) classifier
    gemm_cls<<<MROWS, 128>>>(B2h, B2l, Wc, bc, out);
}